// round 4
// baseline (speedup 1.0000x reference)
#include <cuda_runtime.h>
#include <cuda_bf16.h>

// PairwiseMax: B=4096, D1=256, D2=256, F=128
// out[b, 0:256]   = x0[b,i] >= 0 ? x0[b,i]*max(x1[b,:]) : x0[b,i]*min(x1[b,:])
// out[b, 256:384] = x2[b,:]
//
// R4: exact work distribution. 128 blocks x 1024 threads = 4096 warps =
// one warp per row, one block per SM, zero tail. x2 copy merged into the
// row task; all 5 loads front-batched; x2 store issued before the shuffle
// reduction completes.

#define B_ROWS 4096
#define THREADS 1024
#define BLOCKS (B_ROWS / (THREADS / 32))   // 128

__global__ __launch_bounds__(THREADS) void pairwise_max_kernel(
    const float4* __restrict__ x0v,   // [B, 64] float4
    const float4* __restrict__ x1v,   // [B, 64] float4
    const float4* __restrict__ x2v,   // [B, 32] float4
    float4* __restrict__ outv)        // [B, 96] float4
{
    const int warp_id = threadIdx.x >> 5;
    const int lane    = threadIdx.x & 31;
    const int row     = (blockIdx.x << 5) + warp_id;   // exact: 128*32 = 4096

    const float4* x1row  = x1v + (size_t)row * 64;
    const float4* x0row  = x0v + (size_t)row * 64;
    const float4* x2row  = x2v + (size_t)row * 32;
    float4*       outrow = outv + (size_t)row * 96;

    // Front-batch all 5 independent loads (MLP_p1 = 5 per lane).
    float4 a = x1row[lane];
    float4 b = x1row[lane + 32];
    float4 c = x0row[lane];
    float4 d = x0row[lane + 32];
    float4 e = x2row[lane];

    float mx = fmaxf(fmaxf(fmaxf(a.x, a.y), fmaxf(a.z, a.w)),
                     fmaxf(fmaxf(b.x, b.y), fmaxf(b.z, b.w)));
    float mn = fminf(fminf(fminf(a.x, a.y), fminf(a.z, a.w)),
                     fminf(fminf(b.x, b.y), fminf(b.z, b.w)));

    // x2 passthrough store does not depend on the reduction — drain it early.
    outrow[lane + 64] = e;

    // Two independent shuffle chains interleave in the pipeline.
    #pragma unroll
    for (int off = 16; off > 0; off >>= 1) {
        mx = fmaxf(mx, __shfl_xor_sync(0xFFFFFFFFu, mx, off));
        mn = fminf(mn, __shfl_xor_sync(0xFFFFFFFFu, mn, off));
    }

    float4 oc, od;
    oc.x = c.x * (c.x >= 0.0f ? mx : mn);
    oc.y = c.y * (c.y >= 0.0f ? mx : mn);
    oc.z = c.z * (c.z >= 0.0f ? mx : mn);
    oc.w = c.w * (c.w >= 0.0f ? mx : mn);
    od.x = d.x * (d.x >= 0.0f ? mx : mn);
    od.y = d.y * (d.y >= 0.0f ? mx : mn);
    od.z = d.z * (d.z >= 0.0f ? mx : mn);
    od.w = d.w * (d.w >= 0.0f ? mx : mn);

    outrow[lane]      = oc;
    outrow[lane + 32] = od;
}

extern "C" void kernel_launch(void* const* d_in, const int* in_sizes, int n_in,
                              void* d_out, int out_size)
{
    const float4* x0v = (const float4*)d_in[0];
    const float4* x1v = (const float4*)d_in[1];
    const float4* x2v = (const float4*)d_in[2];
    float4* outv = (float4*)d_out;

    pairwise_max_kernel<<<BLOCKS, THREADS>>>(x0v, x1v, x2v, outv);
}

// round 5
// speedup vs baseline: 1.1354x; 1.1354x over previous
#include <cuda_runtime.h>
#include <cuda_bf16.h>

// PairwiseMax: B=4096, D1=256, D2=256, F=128
// out[b, 0:256]   = x0[b,i] >= 0 ? x0[b,i]*max(x1[b,:]) : x0[b,i]*min(x1[b,:])
// out[b, 256:384] = x2[b,:]
//
// R5: balance fix. R1/R4 both carried a 1.156x busiest-SM penalty
// (512 blocks -> 4-vs-3 per SM; 128 blocks -> 20 idle SMs) and timed
// identically. 4-warp blocks give 1024 blocks -> 7-vs-6 per SM = 1.012x.
// Per-warp body unchanged: warp-per-row, 5 front-batched LDG.128,
// early x2 store, dual-chain shuffle butterfly.

#define B_ROWS 4096
#define WARPS_PER_BLOCK 4
#define THREADS (WARPS_PER_BLOCK * 32)           // 128
#define BLOCKS (B_ROWS / WARPS_PER_BLOCK)        // 1024

__global__ __launch_bounds__(THREADS) void pairwise_max_kernel(
    const float4* __restrict__ x0v,   // [B, 64] float4
    const float4* __restrict__ x1v,   // [B, 64] float4
    const float4* __restrict__ x2v,   // [B, 32] float4
    float4* __restrict__ outv)        // [B, 96] float4
{
    const int warp_id = threadIdx.x >> 5;
    const int lane    = threadIdx.x & 31;
    const int row     = blockIdx.x * WARPS_PER_BLOCK + warp_id;  // exact 4096

    const float4* x1row  = x1v + (size_t)row * 64;
    const float4* x0row  = x0v + (size_t)row * 64;
    const float4* x2row  = x2v + (size_t)row * 32;
    float4*       outrow = outv + (size_t)row * 96;

    // Front-batch all 5 independent loads.
    float4 a = x1row[lane];
    float4 b = x1row[lane + 32];
    float4 c = x0row[lane];
    float4 d = x0row[lane + 32];
    float4 e = x2row[lane];

    float mx = fmaxf(fmaxf(fmaxf(a.x, a.y), fmaxf(a.z, a.w)),
                     fmaxf(fmaxf(b.x, b.y), fmaxf(b.z, b.w)));
    float mn = fminf(fminf(fminf(a.x, a.y), fminf(a.z, a.w)),
                     fminf(fminf(b.x, b.y), fminf(b.z, b.w)));

    // x2 passthrough store does not depend on the reduction — drain it early.
    outrow[lane + 64] = e;

    // Two independent shuffle chains interleave in the pipeline.
    #pragma unroll
    for (int off = 16; off > 0; off >>= 1) {
        mx = fmaxf(mx, __shfl_xor_sync(0xFFFFFFFFu, mx, off));
        mn = fminf(mn, __shfl_xor_sync(0xFFFFFFFFu, mn, off));
    }

    float4 oc, od;
    oc.x = c.x * (c.x >= 0.0f ? mx : mn);
    oc.y = c.y * (c.y >= 0.0f ? mx : mn);
    oc.z = c.z * (c.z >= 0.0f ? mx : mn);
    oc.w = c.w * (c.w >= 0.0f ? mx : mn);
    od.x = d.x * (d.x >= 0.0f ? mx : mn);
    od.y = d.y * (d.y >= 0.0f ? mx : mn);
    od.z = d.z * (d.z >= 0.0f ? mx : mn);
    od.w = d.w * (d.w >= 0.0f ? mx : mn);

    outrow[lane]      = oc;
    outrow[lane + 32] = od;
}

extern "C" void kernel_launch(void* const* d_in, const int* in_sizes, int n_in,
                              void* d_out, int out_size)
{
    const float4* x0v = (const float4*)d_in[0];
    const float4* x1v = (const float4*)d_in[1];
    const float4* x2v = (const float4*)d_in[2];
    float4* outv = (float4*)d_out;

    pairwise_max_kernel<<<BLOCKS, THREADS>>>(x0v, x1v, x2v, outv);
}